// round 1
// baseline (speedup 1.0000x reference)
#include <cuda_runtime.h>
#include <math.h>

#define BB 4
#define NN 8192
#define DIMV 256
#define HH 8
#define HD 32
#define INTERNAL 256
#define MROWS (BB * NN)        // 32768
#define QKVO_COLS 1024

// SCALE = HD^-0.5 = 1/sqrt(32)
#define SCALE_F 0.17677669529663687f

// ---------------- persistent device scratch (no allocations) ----------------
__device__ float g_qkvo[(size_t)MROWS * QKVO_COLS];   // 134 MB
__device__ float g_pre [(size_t)MROWS * INTERNAL];    // 33.5 MB
__device__ float g_kv  [BB * HH * HD * HD];           // per (b,h) 32x32 ks^T v sums
__device__ float g_ksum[BB * HH * HD];                // sum of elu(k)+1
__device__ float g_vsum[BB * HH * HD];                // sum of v

// ---------------- zero accumulators (must be deterministic per call) --------
__global__ void zero_kernel() {
    int i = blockIdx.x * 256 + threadIdx.x;
    if (i < BB * HH * HD * HD) g_kv[i] = 0.f;
    if (i < BB * HH * HD) { g_ksum[i] = 0.f; g_vsum[i] = 0.f; }
}

// ---------------- generic SGEMM: C[M,Nn] = A[M,K] @ Bw[Nn,K]^T + bias -------
// BM=128, BN=64, BK=16, 256 threads, each thread 8x4 micro-tile.
__global__ void __launch_bounds__(256)
sgemm_nt_kernel(const float* __restrict__ A, const float* __restrict__ Bw,
                const float* __restrict__ bias, float* __restrict__ C,
                int M, int Nn, int K)
{
    __shared__ float As[16][128];
    __shared__ float Bs[16][64];

    const int tid = threadIdx.x;
    const int tx = tid & 15;        // N dim, 4 cols each
    const int ty = tid >> 4;        // M dim, 8 rows each
    const int m0 = blockIdx.y * 128;
    const int n0 = blockIdx.x * 64;

    float acc[8][4];
#pragma unroll
    for (int i = 0; i < 8; i++)
#pragma unroll
        for (int j = 0; j < 4; j++) acc[i][j] = 0.f;

    for (int k0 = 0; k0 < K; k0 += 16) {
        // load A tile: 128 rows x 16 cols = 512 float4
#pragma unroll
        for (int i = 0; i < 2; i++) {
            int idx = tid + i * 256;
            int row = idx >> 2;
            int kq  = idx & 3;
            float4 v = *(const float4*)&A[(size_t)(m0 + row) * K + k0 + kq * 4];
            As[kq * 4 + 0][row] = v.x;
            As[kq * 4 + 1][row] = v.y;
            As[kq * 4 + 2][row] = v.z;
            As[kq * 4 + 3][row] = v.w;
        }
        // load B tile: 64 rows x 16 cols = 256 float4
        {
            int row = tid >> 2;
            int kq  = tid & 3;
            float4 v = *(const float4*)&Bw[(size_t)(n0 + row) * K + k0 + kq * 4];
            Bs[kq * 4 + 0][row] = v.x;
            Bs[kq * 4 + 1][row] = v.y;
            Bs[kq * 4 + 2][row] = v.z;
            Bs[kq * 4 + 3][row] = v.w;
        }
        __syncthreads();

#pragma unroll
        for (int kk = 0; kk < 16; kk++) {
            float4 a0 = *(const float4*)&As[kk][ty * 8];
            float4 a1 = *(const float4*)&As[kk][ty * 8 + 4];
            float4 b0 = *(const float4*)&Bs[kk][tx * 4];
            float av[8] = {a0.x, a0.y, a0.z, a0.w, a1.x, a1.y, a1.z, a1.w};
            float bv[4] = {b0.x, b0.y, b0.z, b0.w};
#pragma unroll
            for (int i = 0; i < 8; i++)
#pragma unroll
                for (int j = 0; j < 4; j++)
                    acc[i][j] += av[i] * bv[j];
        }
        __syncthreads();
    }

    float4 bb = *(const float4*)&bias[n0 + tx * 4];
#pragma unroll
    for (int i = 0; i < 8; i++) {
        float4 o;
        o.x = acc[i][0] + bb.x;
        o.y = acc[i][1] + bb.y;
        o.z = acc[i][2] + bb.z;
        o.w = acc[i][3] + bb.w;
        *(float4*)&C[(size_t)(m0 + ty * 8 + i) * Nn + n0 + tx * 4] = o;
    }
}

// ---------------- stats: kv_state / ksum / vsum per (b,h) ------------------
// grid (32 bh, 32 splits), 256 threads. Warp w handles one n per chunk of 8.
__global__ void __launch_bounds__(256)
stats_kernel(const float* __restrict__ qkvo,
             const float* __restrict__ sinp, const float* __restrict__ cosp)
{
    __shared__ float sks[8][32];
    __shared__ float svh[8][32];

    const int bh = blockIdx.x;          // 0..31
    const int split = blockIdx.y;       // 0..31
    const int b = bh >> 3, h = bh & 7;
    const int w = threadIdx.x >> 5;
    const int lane = threadIdx.x & 31;
    const int n_start = split * (NN / 32);

    const int dA = threadIdx.x >> 3;        // kv row   0..31
    const int e4 = (threadIdx.x & 7) * 4;   // kv col base

    float kv0 = 0.f, kv1 = 0.f, kv2 = 0.f, kv3 = 0.f;
    float ksum_acc = 0.f, vsum_acc = 0.f;

    for (int c0 = 0; c0 < NN / 32; c0 += 8) {
        int n = n_start + c0 + w;
        size_t row = (size_t)(b * NN + n) * QKVO_COLS;
        float kraw = qkvo[row + 256 + h * 32 + lane];
        float v    = qkvo[row + 512 + h * 32 + lane];
        float kh = (kraw > 0.f) ? (kraw + 1.f) : expf(kraw);   // elu + 1
        ksum_acc += kh;
        vsum_acc += v;
        float partner = __shfl_xor_sync(0xffffffffu, kh, 1);
        float sv = sinp[n * HD + lane];
        float cv = cosp[n * HD + lane];
        float rot = (lane & 1) ? partner : -partner;
        float ks = kh * cv + rot * sv;                          // theta_shift
        sks[w][lane] = ks;
        svh[w][lane] = v;
        __syncthreads();
#pragma unroll
        for (int j = 0; j < 8; j++) {
            float a = sks[j][dA];
            float4 vv = *(const float4*)&svh[j][e4];
            kv0 += a * vv.x;
            kv1 += a * vv.y;
            kv2 += a * vv.z;
            kv3 += a * vv.w;
        }
        __syncthreads();
    }

    float* kvdst = &g_kv[bh * (HD * HD) + dA * HD + e4];
    atomicAdd(kvdst + 0, kv0);
    atomicAdd(kvdst + 1, kv1);
    atomicAdd(kvdst + 2, kv2);
    atomicAdd(kvdst + 3, kv3);
    atomicAdd(&g_ksum[bh * HD + lane], ksum_acc);
    atomicAdd(&g_vsum[bh * HD + lane], vsum_acc);
}

// ---------------- fused per-token epilogue -> g_pre ------------------------
// block = 64 consecutive n of one batch; 256 threads = channels; warp = head.
#define TILE_ROWS 64
__global__ void __launch_bounds__(256)
fuse_kernel(const float* __restrict__ qkvo,
            const float* __restrict__ sinp, const float* __restrict__ cosp,
            const float* __restrict__ W_lepe, const float* __restrict__ b_lepe,
            float* __restrict__ pre)
{
    __shared__ float skv[HH * HD * HD];   // 32 KB

    const int tile = blockIdx.x;                       // 0 .. B*(N/64)-1
    const int b  = tile / (NN / TILE_ROWS);
    const int t  = tile % (NN / TILE_ROWS);
    const int n0 = t * TILE_ROWS;
    const int c  = threadIdx.x;
    const int h  = c >> 5;
    const int d  = c & 31;                             // acts as dim index & "e" lane
    const float inv_scale_n = SCALE_F / (float)NN;

    // load kv_state for this batch, scaled by SCALE/N (the s^2 factor)
    const int base_kv = b * HH * HD * HD;
    for (int i = c; i < HH * HD * HD; i += 256)
        skv[i] = g_kv[base_kv + i] * inv_scale_n;

    const float km = g_ksum[(b * HH + h) * HD + d];              // raw sum
    const float vm = g_vsum[(b * HH + h) * HD + d] * (1.f / NN); // mean
    __syncthreads();

    const float w0 = W_lepe[c * 3 + 0];
    const float w1 = W_lepe[c * 3 + 1];
    const float w2 = W_lepe[c * 3 + 2];
    const float bl = b_lepe[c];

    size_t rowbase = (size_t)(b * NN + n0) * QKVO_COLS;
    float v_prev = (n0 > 0) ? qkvo[rowbase - QKVO_COLS + 512 + c] : 0.f;
    float v_cur  = qkvo[rowbase + 512 + c];

    const float* kvh = &skv[h * HD * HD];

    for (int r = 0; r < TILE_ROWS; r++) {
        int n = n0 + r;
        size_t row = (size_t)(b * NN + n) * QKVO_COLS;
        float v_next = (n + 1 < NN) ? qkvo[row + QKVO_COLS + 512 + c] : 0.f;

        float q  = qkvo[row + c];
        float qh = (q > 0.f) ? (q + 1.f) : expf(q);   // elu + 1

        // z = SCALE * dot(qh, kmean) = (SCALE/N) * dot(qh, ksum)
        float zp = qh * km;
#pragma unroll
        for (int off = 16; off > 0; off >>= 1)
            zp += __shfl_xor_sync(0xffffffffu, zp, off);
        float z = zp * inv_scale_n;

        // theta_shift(qh)
        float partner = __shfl_xor_sync(0xffffffffu, qh, 1);
        float sv = sinp[n * HD + d];
        float cv = cosp[n * HD + d];
        float rot = (d & 1) ? partner : -partner;
        float qs = qh * cv + rot * sv;

        // attn_out[e=d] = sum_dd qs[dd] * kv[dd][d]
        float acc = 0.f;
#pragma unroll
        for (int dd = 0; dd < 32; dd++) {
            float qsd = __shfl_sync(0xffffffffu, qs, dd);
            acc += qsd * kvh[dd * HD + d];
        }

        float coef = 1.f + 1.f / (z + 1e-6f);
        float res  = acc * coef - z * vm;
        float lepe = v_prev * w0 + v_cur * w1 + v_next * w2 + bl;
        float o    = qkvo[row + 768 + c];

        pre[(size_t)(b * NN + n) * INTERNAL + c] = (res + lepe) * o;

        v_prev = v_cur;
        v_cur  = v_next;
    }
}

// ---------------- launch -----------------------------------------------------
extern "C" void kernel_launch(void* const* d_in, const int* in_sizes, int n_in,
                              void* d_out, int out_size)
{
    const float* x       = (const float*)d_in[0];
    const float* sinp    = (const float*)d_in[1];
    const float* cosp    = (const float*)d_in[2];
    const float* W_qkvo  = (const float*)d_in[3];
    const float* b_qkvo  = (const float*)d_in[4];
    const float* W_lepe  = (const float*)d_in[5];
    const float* b_lepe  = (const float*)d_in[6];
    const float* W_proj  = (const float*)d_in[7];
    const float* b_proj  = (const float*)d_in[8];
    float* out = (float*)d_out;

    float *qkvo_p, *pre_p;
    cudaGetSymbolAddress((void**)&qkvo_p, g_qkvo);
    cudaGetSymbolAddress((void**)&pre_p,  g_pre);

    zero_kernel<<<(BB * HH * HD * HD + 255) / 256, 256>>>();

    // GEMM1: qkvo = x @ W_qkvo^T + b_qkvo   [32768 x 1024]
    sgemm_nt_kernel<<<dim3(QKVO_COLS / 64, MROWS / 128), 256>>>(
        x, W_qkvo, b_qkvo, qkvo_p, MROWS, QKVO_COLS, DIMV);

    // per-(b,h) reductions
    stats_kernel<<<dim3(BB * HH, 32), 256>>>(qkvo_p, sinp, cosp);

    // fused epilogue -> pre
    fuse_kernel<<<BB * (NN / TILE_ROWS), 256>>>(qkvo_p, sinp, cosp,
                                                W_lepe, b_lepe, pre_p);

    // GEMM2: out = pre @ W_proj^T + b_proj  [32768 x 256]
    sgemm_nt_kernel<<<dim3(INTERNAL / 64, MROWS / 128), 256>>>(
        pre_p, W_proj, b_proj, out, MROWS, INTERNAL, DIMV);
}

// round 3
// speedup vs baseline: 1.7149x; 1.7149x over previous
#include <cuda_runtime.h>
#include <cuda_bf16.h>
#include <math.h>
#include <stdint.h>

#define BB 4
#define NN 8192
#define DIMV 256
#define HH 8
#define HD 32
#define INTERNAL 256
#define MROWS (BB * NN)        // 32768
#define QKVO_COLS 1024
#define SCALE_F 0.17677669529663687f

// ---------------- persistent device scratch (no allocations) ----------------
__device__ float g_qkvo[(size_t)MROWS * QKVO_COLS];   // 134 MB
__device__ float g_pre [(size_t)MROWS * INTERNAL];    // 33.5 MB
__device__ float g_kv  [BB * HH * HD * HD];
__device__ float g_ksum[BB * HH * HD];
__device__ float g_vsum[BB * HH * HD];

__device__ __forceinline__ uint32_t smem_u32(const void* p) {
    uint32_t a;
    asm("{ .reg .u64 t; cvta.to.shared.u64 t, %1; cvt.u32.u64 %0, t; }"
        : "=r"(a) : "l"(p));
    return a;
}

__device__ __forceinline__ void split2(float a, float b, uint32_t& hi, uint32_t& lo) {
    __nv_bfloat162 h = __floats2bfloat162_rn(a, b);
    float ra = a - __bfloat162float(h.x);
    float rb = b - __bfloat162float(h.y);
    __nv_bfloat162 l = __floats2bfloat162_rn(ra, rb);
    hi = *reinterpret_cast<uint32_t*>(&h);
    lo = *reinterpret_cast<uint32_t*>(&l);
}

__device__ __forceinline__ void ldmx4(uint32_t* r, uint32_t addr) {
    asm volatile("ldmatrix.sync.aligned.m8n8.x4.shared.b16 {%0,%1,%2,%3}, [%4];"
        : "=r"(r[0]), "=r"(r[1]), "=r"(r[2]), "=r"(r[3]) : "r"(addr));
}

__device__ __forceinline__ void mma16816(float* d, const uint32_t* a,
                                         uint32_t b0, uint32_t b1) {
    asm volatile(
        "mma.sync.aligned.m16n8k16.row.col.f32.bf16.bf16.f32 "
        "{%0,%1,%2,%3}, {%4,%5,%6,%7}, {%8,%9}, {%0,%1,%2,%3};"
        : "+f"(d[0]), "+f"(d[1]), "+f"(d[2]), "+f"(d[3])
        : "r"(a[0]), "r"(a[1]), "r"(a[2]), "r"(a[3]), "r"(b0), "r"(b1));
}

// =================== HMMA GEMM: C[M,Nn] = A[M,K] @ Bw[Nn,K]^T + bias ========
// 128x128 tile, BK=32, 8 warps (4M x 2N), warp tile 32x64.
// 3-term bf16 split. Smem rows padded to 80B (40 bf16) -> conflict-free ldmatrix.
#define ROWB 80                 // bytes per smem row (32 bf16 + pad)
#define A_HI 0
#define A_LO 10240
#define B_HI 20480
#define B_LO 30720
#define BUFB 40960
#define GEMM_SMEM_BYTES (2 * BUFB)   // 80 KB

__global__ void __launch_bounds__(256)
gemm_mma_kernel(const float* __restrict__ A, const float* __restrict__ Bw,
                const float* __restrict__ bias, float* __restrict__ C,
                int M, int Nn, int K)
{
    extern __shared__ char sm[];
    const uint32_t smb = smem_u32(sm);
    const int tid  = threadIdx.x;
    const int wid  = tid >> 5;
    const int lane = tid & 31;
    const int m0 = blockIdx.y * 128;
    const int n0 = blockIdx.x * 128;
    const int wm0 = (wid & 3) * 32;
    const int wn0 = (wid >> 2) * 64;

    // per-lane ldmatrix offsets
    const int a_row = (lane & 7) + ((lane >> 3) & 1) * 8;
    const int a_kh  = (lane >> 4) * 8;
    const int b_row = (lane & 7) + ((lane >> 4) & 1) * 8;
    const int b_kh  = ((lane >> 3) & 1) * 8;

    float acc[2][8][4];
#pragma unroll
    for (int i = 0; i < 2; i++)
#pragma unroll
        for (int j = 0; j < 8; j++)
#pragma unroll
            for (int l = 0; l < 4; l++) acc[i][j][l] = 0.f;

    const int NCH = K / 32;
    const int row_g = tid >> 3;          // 0..31 within 256-thread slab
    const int q_g   = tid & 7;           // which float4 in the 32-float row

    float4 stA[4], stB[4];

    // ---- prologue: load chunk 0 ----
#pragma unroll
    for (int i = 0; i < 4; i++) {
        int r = row_g + i * 32;
        stA[i] = *(const float4*)&A [(size_t)(m0 + r) * K + q_g * 4];
        stB[i] = *(const float4*)&Bw[(size_t)(n0 + r) * K + q_g * 4];
    }
    {
        char* buf = sm;
#pragma unroll
        for (int i = 0; i < 4; i++) {
            int r = row_g + i * 32;
            uint2 hi, lo;
            split2(stA[i].x, stA[i].y, hi.x, lo.x);
            split2(stA[i].z, stA[i].w, hi.y, lo.y);
            *(uint2*)(buf + A_HI + r * ROWB + q_g * 8) = hi;
            *(uint2*)(buf + A_LO + r * ROWB + q_g * 8) = lo;
            split2(stB[i].x, stB[i].y, hi.x, lo.x);
            split2(stB[i].z, stB[i].w, hi.y, lo.y);
            *(uint2*)(buf + B_HI + r * ROWB + q_g * 8) = hi;
            *(uint2*)(buf + B_LO + r * ROWB + q_g * 8) = lo;
        }
    }
    __syncthreads();

    for (int c = 0; c < NCH; c++) {
        if (c + 1 < NCH) {
            int k0 = (c + 1) * 32;
#pragma unroll
            for (int i = 0; i < 4; i++) {
                int r = row_g + i * 32;
                stA[i] = *(const float4*)&A [(size_t)(m0 + r) * K + k0 + q_g * 4];
                stB[i] = *(const float4*)&Bw[(size_t)(n0 + r) * K + k0 + q_g * 4];
            }
        }

        // ---- MMA over current buffer ----
        const uint32_t base = smb + (c & 1) * BUFB;
#pragma unroll
        for (int ks = 0; ks < 2; ks++) {
            uint32_t ah[2][4], al[2][4];
#pragma unroll
            for (int mf = 0; mf < 2; mf++) {
                uint32_t ao = base + (wm0 + mf * 16 + a_row) * ROWB
                            + (ks * 16 + a_kh) * 2;
                ldmx4(ah[mf], ao + A_HI);
                ldmx4(al[mf], ao + A_LO);
            }
#pragma unroll
            for (int nf2 = 0; nf2 < 4; nf2++) {
                uint32_t bo = base + (wn0 + nf2 * 16 + b_row) * ROWB
                            + (ks * 16 + b_kh) * 2;
                uint32_t bh[4], bl[4];
                ldmx4(bh, bo + B_HI);
                ldmx4(bl, bo + B_LO);
#pragma unroll
                for (int mf = 0; mf < 2; mf++) {
#pragma unroll
                    for (int s = 0; s < 2; s++) {
                        float* d = acc[mf][nf2 * 2 + s];
                        mma16816(d, ah[mf], bh[s * 2], bh[s * 2 + 1]);
                        mma16816(d, al[mf], bh[s * 2], bh[s * 2 + 1]);
                        mma16816(d, ah[mf], bl[s * 2], bl[s * 2 + 1]);
                    }
                }
            }
        }

        if (c + 1 < NCH) {
            char* buf = sm + ((c + 1) & 1) * BUFB;
#pragma unroll
            for (int i = 0; i < 4; i++) {
                int r = row_g + i * 32;
                uint2 hi, lo;
                split2(stA[i].x, stA[i].y, hi.x, lo.x);
                split2(stA[i].z, stA[i].w, hi.y, lo.y);
                *(uint2*)(buf + A_HI + r * ROWB + q_g * 8) = hi;
                *(uint2*)(buf + A_LO + r * ROWB + q_g * 8) = lo;
                split2(stB[i].x, stB[i].y, hi.x, lo.x);
                split2(stB[i].z, stB[i].w, hi.y, lo.y);
                *(uint2*)(buf + B_HI + r * ROWB + q_g * 8) = hi;
                *(uint2*)(buf + B_LO + r * ROWB + q_g * 8) = lo;
            }
        }
        __syncthreads();
    }

    // ---- epilogue: direct stores (float2) + bias ----
    const int rr = lane >> 2;
    const int cc = (lane & 3) * 2;
#pragma unroll
    for (int mf = 0; mf < 2; mf++) {
        int r0 = m0 + wm0 + mf * 16 + rr;
#pragma unroll
        for (int nf = 0; nf < 8; nf++) {
            int col = n0 + wn0 + nf * 8 + cc;
            float b0 = bias[col], b1 = bias[col + 1];
            float2 v0 = {acc[mf][nf][0] + b0, acc[mf][nf][1] + b1};
            float2 v1 = {acc[mf][nf][2] + b0, acc[mf][nf][3] + b1};
            *(float2*)&C[(size_t)r0 * Nn + col] = v0;
            *(float2*)&C[(size_t)(r0 + 8) * Nn + col] = v1;
        }
    }
}

// ---------------- zero accumulators ----------------------------------------
__global__ void zero_kernel() {
    int i = blockIdx.x * 256 + threadIdx.x;
    if (i < BB * HH * HD * HD) g_kv[i] = 0.f;
    if (i < BB * HH * HD) { g_ksum[i] = 0.f; g_vsum[i] = 0.f; }
}

// ---------------- stats: kv_state / ksum / vsum per (b,h) ------------------
__global__ void __launch_bounds__(256)
stats_kernel(const float* __restrict__ qkvo,
             const float* __restrict__ sinp, const float* __restrict__ cosp)
{
    __shared__ float sks[8][32];
    __shared__ float svh[8][32];

    const int bh = blockIdx.x;
    const int split = blockIdx.y;
    const int b = bh >> 3, h = bh & 7;
    const int w = threadIdx.x >> 5;
    const int lane = threadIdx.x & 31;
    const int n_start = split * (NN / 32);

    const int dA = threadIdx.x >> 3;
    const int e4 = (threadIdx.x & 7) * 4;

    float kv0 = 0.f, kv1 = 0.f, kv2 = 0.f, kv3 = 0.f;
    float ksum_acc = 0.f, vsum_acc = 0.f;

    for (int c0 = 0; c0 < NN / 32; c0 += 8) {
        int n = n_start + c0 + w;
        size_t row = (size_t)(b * NN + n) * QKVO_COLS;
        float kraw = qkvo[row + 256 + h * 32 + lane];
        float v    = qkvo[row + 512 + h * 32 + lane];
        float kh = (kraw > 0.f) ? (kraw + 1.f) : expf(kraw);
        ksum_acc += kh;
        vsum_acc += v;
        float partner = __shfl_xor_sync(0xffffffffu, kh, 1);
        float sv = sinp[n * HD + lane];
        float cv = cosp[n * HD + lane];
        float rot = (lane & 1) ? partner : -partner;
        float ks = kh * cv + rot * sv;
        sks[w][lane] = ks;
        svh[w][lane] = v;
        __syncthreads();
#pragma unroll
        for (int j = 0; j < 8; j++) {
            float a = sks[j][dA];
            float4 vv = *(const float4*)&svh[j][e4];
            kv0 += a * vv.x;
            kv1 += a * vv.y;
            kv2 += a * vv.z;
            kv3 += a * vv.w;
        }
        __syncthreads();
    }

    float* kvdst = &g_kv[bh * (HD * HD) + dA * HD + e4];
    atomicAdd(kvdst + 0, kv0);
    atomicAdd(kvdst + 1, kv1);
    atomicAdd(kvdst + 2, kv2);
    atomicAdd(kvdst + 3, kv3);
    atomicAdd(&g_ksum[bh * HD + lane], ksum_acc);
    atomicAdd(&g_vsum[bh * HD + lane], vsum_acc);
}

// ---------------- fused per-token epilogue -> g_pre ------------------------
#define TILE_ROWS 64
__global__ void __launch_bounds__(256)
fuse_kernel(const float* __restrict__ qkvo,
            const float* __restrict__ sinp, const float* __restrict__ cosp,
            const float* __restrict__ W_lepe, const float* __restrict__ b_lepe,
            float* __restrict__ pre)
{
    __shared__ float skv[HH * HD * HD];

    const int tile = blockIdx.x;
    const int b  = tile / (NN / TILE_ROWS);
    const int t  = tile % (NN / TILE_ROWS);
    const int n0 = t * TILE_ROWS;
    const int c  = threadIdx.x;
    const int h  = c >> 5;
    const int d  = c & 31;
    const float inv_scale_n = SCALE_F / (float)NN;

    const int base_kv = b * HH * HD * HD;
    for (int i = c; i < HH * HD * HD; i += 256)
        skv[i] = g_kv[base_kv + i] * inv_scale_n;

    const float km = g_ksum[(b * HH + h) * HD + d];
    const float vm = g_vsum[(b * HH + h) * HD + d] * (1.f / NN);
    __syncthreads();

    const float w0 = W_lepe[c * 3 + 0];
    const float w1 = W_lepe[c * 3 + 1];
    const float w2 = W_lepe[c * 3 + 2];
    const float bl = b_lepe[c];

    size_t rowbase = (size_t)(b * NN + n0) * QKVO_COLS;
    float v_prev = (n0 > 0) ? qkvo[rowbase - QKVO_COLS + 512 + c] : 0.f;
    float v_cur  = qkvo[rowbase + 512 + c];

    const float* kvh = &skv[h * HD * HD];

    for (int r = 0; r < TILE_ROWS; r++) {
        int n = n0 + r;
        size_t row = (size_t)(b * NN + n) * QKVO_COLS;
        float v_next = (n + 1 < NN) ? qkvo[row + QKVO_COLS + 512 + c] : 0.f;

        float q  = qkvo[row + c];
        float qh = (q > 0.f) ? (q + 1.f) : expf(q);

        float zp = qh * km;
#pragma unroll
        for (int off = 16; off > 0; off >>= 1)
            zp += __shfl_xor_sync(0xffffffffu, zp, off);
        float z = zp * inv_scale_n;

        float partner = __shfl_xor_sync(0xffffffffu, qh, 1);
        float sv = sinp[n * HD + d];
        float cv = cosp[n * HD + d];
        float rot = (d & 1) ? partner : -partner;
        float qs = qh * cv + rot * sv;

        float acc = 0.f;
#pragma unroll
        for (int dd = 0; dd < 32; dd++) {
            float qsd = __shfl_sync(0xffffffffu, qs, dd);
            acc += qsd * kvh[dd * HD + d];
        }

        float coef = 1.f + 1.f / (z + 1e-6f);
        float res  = acc * coef - z * vm;
        float lepe = v_prev * w0 + v_cur * w1 + v_next * w2 + bl;
        float o    = qkvo[row + 768 + c];

        pre[(size_t)(b * NN + n) * INTERNAL + c] = (res + lepe) * o;

        v_prev = v_cur;
        v_cur  = v_next;
    }
}

// ---------------- launch -----------------------------------------------------
extern "C" void kernel_launch(void* const* d_in, const int* in_sizes, int n_in,
                              void* d_out, int out_size)
{
    const float* x       = (const float*)d_in[0];
    const float* sinp    = (const float*)d_in[1];
    const float* cosp    = (const float*)d_in[2];
    const float* W_qkvo  = (const float*)d_in[3];
    const float* b_qkvo  = (const float*)d_in[4];
    const float* W_lepe  = (const float*)d_in[5];
    const float* b_lepe  = (const float*)d_in[6];
    const float* W_proj  = (const float*)d_in[7];
    const float* b_proj  = (const float*)d_in[8];
    float* out = (float*)d_out;

    float *qkvo_p, *pre_p;
    cudaGetSymbolAddress((void**)&qkvo_p, g_qkvo);
    cudaGetSymbolAddress((void**)&pre_p,  g_pre);

    cudaFuncSetAttribute(gemm_mma_kernel,
                         cudaFuncAttributeMaxDynamicSharedMemorySize, GEMM_SMEM_BYTES);

    zero_kernel<<<(BB * HH * HD * HD + 255) / 256, 256>>>();

    // GEMM1: qkvo = x @ W_qkvo^T + b_qkvo   [32768 x 1024]
    gemm_mma_kernel<<<dim3(QKVO_COLS / 128, MROWS / 128), 256, GEMM_SMEM_BYTES>>>(
        x, W_qkvo, b_qkvo, qkvo_p, MROWS, QKVO_COLS, DIMV);

    // per-(b,h) reductions
    stats_kernel<<<dim3(BB * HH, 32), 256>>>(qkvo_p, sinp, cosp);

    // fused epilogue -> pre
    fuse_kernel<<<BB * (NN / TILE_ROWS), 256>>>(qkvo_p, sinp, cosp,
                                                W_lepe, b_lepe, pre_p);

    // GEMM2: out = pre @ W_proj^T + b_proj  [32768 x 256]
    gemm_mma_kernel<<<dim3(INTERNAL / 128, MROWS / 128), 256, GEMM_SMEM_BYTES>>>(
        pre_p, W_proj, b_proj, out, MROWS, INTERNAL, DIMV);
}